// round 8
// baseline (speedup 1.0000x reference)
#include <cuda_runtime.h>
#include <cstdint>

// Spatial correlation sampler: out[b][dy][dx][y][x] =
//   sum_c in1[b,c,y,x] * in2[b,c,y+dy-4,x+dx-4]   (zero padded), dy,dx in 0..8
//
// Round-8: 2 pixels per thread (acc 54 regs) -> 18 warps / 576 threads per
// block at ~<=112 regs => 4.5 warps/SMSP (2x round-7 latency hiding).
// Warp = (ri, g, x-half); lane = 2 px; 27 f32x2 accumulators per thread.
// cp.async triple-buffered SMEM pipeline, 2 channels/stage, padded in2 rows.

#define CC 128
#define HH 96
#define WW 128
#define HW (HH * WW)

#define NTHR   576          // 18 warps: (xh 2) x (ri 3) x (g 3)
#define STAGES 64           // 2 channels per stage
#define W2     136          // padded row: 4 + 128 + 4 floats
#define CHF    (14 * W2)    // floats per channel slab (3 in2 + 11 in1 rows)
#define BUFF   (2 * CHF)    // floats per stage buffer
#define BUFB   (BUFF * 4)   // bytes per stage buffer

typedef unsigned long long ull;

__device__ __forceinline__ void fma2(ull& acc, ull a, ull b) {
    asm("fma.rn.f32x2 %0, %1, %2, %0;" : "+l"(acc) : "l"(a), "l"(b));
}

// pair (lo = hi of a, hi = lo of b)
__device__ __forceinline__ ull pkmid(ull a, ull b) {
    ull r;
    asm("{ .reg .b32 al, ah, bl, bh;\n\t"
        "  mov.b64 {al, ah}, %1;\n\t"
        "  mov.b64 {bl, bh}, %2;\n\t"
        "  mov.b64 %0, {ah, bl}; }"
        : "=l"(r) : "l"(a), "l"(b));
    return r;
}

__device__ __forceinline__ float2 unpk(ull v) {
    unsigned lo, hi;
    asm("mov.b64 {%0,%1}, %2;" : "=r"(lo), "=r"(hi) : "l"(v));
    return make_float2(__uint_as_float(lo), __uint_as_float(hi));
}

__device__ __forceinline__ void cp16(uint32_t dst, const float* src) {
    asm volatile("cp.async.cg.shared.global [%0], [%1], 16;"
                 :: "r"(dst), "l"(src) : "memory");
}

__device__ __forceinline__ int clampi(int v, int lo, int hi) {
    return v < lo ? lo : (v > hi ? hi : v);
}

__global__ __launch_bounds__(NTHR, 1) void corr_kernel(
    const float* __restrict__ in1,
    const float* __restrict__ in2,
    float* __restrict__ out)
{
    // [buf(3)][ch(2)][row(14)][col(136)]; rows 0..2 = in2 (padded pair cols),
    // rows 3..13 = in1 (data at col offset +4 like in2)
    __shared__ float sm[3 * BUFF];

    const int tid  = threadIdx.x;
    const int lane = tid & 31;
    const int w    = tid >> 5;          // 0..17
    const int xh   = w / 9;             // x half
    const int w9   = w % 9;
    const int g    = w9 % 3;            // dy group: dy = 3g..3g+2
    const int ri   = w9 / 3;            // 0..2: in2 row of the tile
    const int b    = blockIdx.y;
    const int r0   = blockIdx.x * 3 - 4;
    const int r    = r0 + ri;           // in2 row, -4..100
    const int x0   = 2 * lane + 64 * xh;

    const float rowok = (r >= 0 && r < HH) ? 1.0f : 0.0f;

    const float* p1base = in1 + (size_t)b * CC * HW;
    const float* p2base = in2 + (size_t)b * CC * HW;
    const uint32_t smb = (uint32_t)__cvta_generic_to_shared(sm);

    // ---- zero in2 pad columns in all 3 buffers (once) ----
    if (tid < 144) {
        const int bu = tid / 48, q = tid % 48;
        const int ch = q / 24, q2 = q % 24;
        const int rw = q2 / 8, k = q2 & 7;
        sm[(size_t)bu * BUFF + (ch * 14 + rw) * W2 + (k < 4 ? k : 128 + k)] = 0.0f;
    }

    // ---- precompute fill slots: 896 16B chunks / 576 threads ----
    // warps 0..9 have 2 slots, warps 10..17 have 1 (warp-uniform)
    const float* ssrc[2];
    uint32_t     sdst[2];
    const int nslots = (w < 10) ? 2 : 1;
    #pragma unroll
    for (int j = 0; j < 2; j++) {
        const int n = tid + 576 * j;
        if (n < 896) {
            const int ch = n / 448, rem = n % 448;
            const int rr = rem >> 5, k = rem & 31;
            int srow;
            const float* base;
            if (rr < 3) {
                srow = clampi(r0 + rr, 0, HH - 1);
                base = p2base;
            } else {
                srow = clampi(r0 - 4 + (rr - 3), 0, HH - 1);
                base = p1base;
            }
            ssrc[j] = base + (size_t)ch * HW + (size_t)srow * WW + (k << 2);
            sdst[j] = smb + (((ch * 14 + rr) * W2 + 4 + (k << 2)) << 2); // buf 0
        }
    }

    #define FILL(BUF, S)                                              \
        do {                                                          \
            const size_t co = (size_t)(2 * (S)) * HW;                 \
            const uint32_t bo = (uint32_t)(BUF) * BUFB;               \
            _Pragma("unroll")                                         \
            for (int j = 0; j < 2; j++)                               \
                if (j < nslots) cp16(sdst[j] + bo, ssrc[j] + co);     \
            asm volatile("cp.async.commit_group;" ::: "memory");      \
        } while (0)

    // 27 accumulators: pair over the 2 pixels
    ull acc[3][9];
    #pragma unroll
    for (int t = 0; t < 3; t++)
        #pragma unroll
        for (int d = 0; d < 9; d++)
            acc[t][d] = 0ull;

    // compute-side smem float offsets (buffer 0, channel 0)
    const int jbase = ri + 8 - 3 * g;            // 2..10
    const int winf  = ri * W2 + x0;              // window floats: s2row[x0..x0+9]
    int af[3];
    #pragma unroll
    for (int t = 0; t < 3; t++)
        af[t] = (3 + jbase - t) * W2 + 4 + x0;

    FILL(0, 0);
    FILL(1, 1);

    int bufc = 0;   // s % 3
    int buff = 2;   // (s+2) % 3

    #pragma unroll 1
    for (int s = 0; s < STAGES; s++) {
        if (s < STAGES - 1)
            asm volatile("cp.async.wait_group 1;" ::: "memory");
        else
            asm volatile("cp.async.wait_group 0;" ::: "memory");
        __syncthreads();

        const int boff = bufc * BUFF;
        #pragma unroll
        for (int u = 0; u < 2; u++) {
            const float* base = sm + boff + u * CHF;
            // window: 5 non-overlapping ull pairs = floats x0-4 .. x0+5
            const ull* uw = (const ull*)(base + winf);
            const ull u0 = uw[0], u1 = uw[1], u2 = uw[2], u3 = uw[3], u4 = uw[4];
            const ull A0 = *(const ull*)(base + af[0]);
            const ull A1 = *(const ull*)(base + af[1]);
            const ull A2 = *(const ull*)(base + af[2]);

            ull wp[9];
            wp[0] = u0;  wp[2] = u1;  wp[4] = u2;  wp[6] = u3;  wp[8] = u4;
            wp[1] = pkmid(u0, u1);
            wp[3] = pkmid(u1, u2);
            wp[5] = pkmid(u2, u3);
            wp[7] = pkmid(u3, u4);

            #pragma unroll
            for (int d = 0; d < 9; d++) {
                fma2(acc[0][d], A0, wp[d]);
                fma2(acc[1][d], A1, wp[d]);
                fma2(acc[2][d], A2, wp[d]);
            }
        }

        // fill buffer (s+2)%3: last consumed at stage s-1, ordered by this
        // stage's top barrier -> no second barrier needed
        if (s + 2 < STAGES) FILL(buff, s + 2);

        bufc = (bufc == 2) ? 0 : bufc + 1;
        buff = (buff == 2) ? 0 : buff + 1;
    }
    #undef FILL

    // ---- epilogue: x-boundary zeros came free from smem pads ----
    #pragma unroll
    for (int t = 0; t < 3; t++) {
        const int y = r + 4 - (3 * g + t);
        if (y < 0 || y >= HH) continue;        // warp-uniform
        const int dy = 3 * g + t;
        #pragma unroll
        for (int d = 0; d < 9; d++) {
            const float2 v = unpk(acc[t][d]);
            float* po = out + (((((size_t)b * 9 + dy) * 9 + d) * HH + y) * WW) + x0;
            *(float2*)po = make_float2(v.x * rowok, v.y * rowok);
        }
    }
}

extern "C" void kernel_launch(void* const* d_in, const int* in_sizes, int n_in,
                              void* d_out, int out_size)
{
    const float* in1 = (const float*)d_in[0];
    const float* in2 = (const float*)d_in[1];
    float* out = (float*)d_out;

    // blockIdx.x = r-tile (35 tiles cover r = -4..100), blockIdx.y = batch
    dim3 grid(35, 8, 1);
    corr_kernel<<<grid, NTHR>>>(in1, in2, out);
}

// round 9
// speedup vs baseline: 1.0254x; 1.0254x over previous
#include <cuda_runtime.h>
#include <cstdint>

// Spatial correlation sampler: out[b][dy][dx][y][x] =
//   sum_c in1[b,c,y,x] * in2[b,c,y+dy-4,x+dx-4]   (zero padded), dy,dx in 0..8
//
// Round-9: r8 layout (18 warps, 2 px/thread, 27 f32x2 accumulators, cp.async
// triple-buffered smem pipeline) with FOUR channels per stage:
//   - barriers + wait_groups halved (64 -> 32)
//   - fill issued right after the top barrier (overlaps compute)
//   - dynamic smem 91.4 KB (3 bufs x 4 ch x 14 rows x 136 floats)

#define CC 128
#define HH 96
#define WW 128
#define HW (HH * WW)

#define NTHR    576          // 18 warps: (xh 2) x (ri 3) x (g 3)
#define CHPS    4            // channels per stage
#define STAGES  (CC / CHPS)  // 32
#define W2      136          // padded row: 4 + 128 + 4 floats
#define CHF     (14 * W2)    // floats per channel slab (3 in2 + 11 in1 rows)
#define BUFF    (CHPS * CHF) // floats per stage buffer
#define BUFB    (BUFF * 4)   // bytes per stage buffer
#define SMEMB   (3 * BUFB)   // total dynamic smem bytes (91392)
#define NCHUNK  (CHPS * 448) // 16B chunks per stage (1792)

typedef unsigned long long ull;

__device__ __forceinline__ void fma2(ull& acc, ull a, ull b) {
    asm("fma.rn.f32x2 %0, %1, %2, %0;" : "+l"(acc) : "l"(a), "l"(b));
}

// pair (lo = hi of a, hi = lo of b)
__device__ __forceinline__ ull pkmid(ull a, ull b) {
    ull r;
    asm("{ .reg .b32 al, ah, bl, bh;\n\t"
        "  mov.b64 {al, ah}, %1;\n\t"
        "  mov.b64 {bl, bh}, %2;\n\t"
        "  mov.b64 %0, {ah, bl}; }"
        : "=l"(r) : "l"(a), "l"(b));
    return r;
}

__device__ __forceinline__ float2 unpk(ull v) {
    unsigned lo, hi;
    asm("mov.b64 {%0,%1}, %2;" : "=r"(lo), "=r"(hi) : "l"(v));
    return make_float2(__uint_as_float(lo), __uint_as_float(hi));
}

__device__ __forceinline__ void cp16(uint32_t dst, const float* src) {
    asm volatile("cp.async.cg.shared.global [%0], [%1], 16;"
                 :: "r"(dst), "l"(src) : "memory");
}

__device__ __forceinline__ int clampi(int v, int lo, int hi) {
    return v < lo ? lo : (v > hi ? hi : v);
}

__global__ __launch_bounds__(NTHR, 1) void corr_kernel(
    const float* __restrict__ in1,
    const float* __restrict__ in2,
    float* __restrict__ out)
{
    // [buf(3)][ch(4)][row(14)][col(136)]; rows 0..2 = in2 (padded cols),
    // rows 3..13 = in1 (data at col offset +4 like in2)
    extern __shared__ float sm[];

    const int tid  = threadIdx.x;
    const int lane = tid & 31;
    const int w    = tid >> 5;          // 0..17
    const int xh   = w / 9;             // x half
    const int w9   = w % 9;
    const int g    = w9 % 3;            // dy group: dy = 3g..3g+2
    const int ri   = w9 / 3;            // 0..2: in2 row of the tile
    const int b    = blockIdx.y;
    const int r0   = blockIdx.x * 3 - 4;
    const int r    = r0 + ri;           // in2 row, -4..100
    const int x0   = 2 * lane + 64 * xh;

    const float rowok = (r >= 0 && r < HH) ? 1.0f : 0.0f;

    const float* p1base = in1 + (size_t)b * CC * HW;
    const float* p2base = in2 + (size_t)b * CC * HW;
    const uint32_t smb = (uint32_t)__cvta_generic_to_shared(sm);

    // ---- zero in2 pad columns in all 3 buffers x 4 channels (once) ----
    if (tid < 288) {
        const int bu = tid / 96, q = tid % 96;
        const int ch = q / 24, q2 = q % 24;
        const int rw = q2 / 8, k = q2 & 7;
        sm[(size_t)bu * BUFF + (ch * 14 + rw) * W2 + (k < 4 ? k : 128 + k)] = 0.0f;
    }

    // ---- precompute fill slots: 1792 16B chunks / 576 threads ----
    // tid < 64 (warps 0,1): 4 slots; others: 3 (warp-uniform)
    const float* ssrc[4];
    uint32_t     sdst[4];
    const int nslots = (tid < NCHUNK - 3 * NTHR) ? 4 : 3;
    #pragma unroll
    for (int j = 0; j < 4; j++) {
        const int n = tid + NTHR * j;
        if (n < NCHUNK) {
            const int ch = n / 448, rem = n % 448;
            const int rr = rem >> 5, k = rem & 31;
            int srow;
            const float* base;
            if (rr < 3) {
                srow = clampi(r0 + rr, 0, HH - 1);
                base = p2base;
            } else {
                srow = clampi(r0 - 4 + (rr - 3), 0, HH - 1);
                base = p1base;
            }
            ssrc[j] = base + (size_t)ch * HW + (size_t)srow * WW + (k << 2);
            sdst[j] = smb + (((ch * 14 + rr) * W2 + 4 + (k << 2)) << 2); // buf 0
        }
    }

    #define FILL(BUF, S)                                              \
        do {                                                          \
            const size_t co = (size_t)(CHPS * (S)) * HW;              \
            const uint32_t bo = (uint32_t)(BUF) * BUFB;               \
            _Pragma("unroll")                                         \
            for (int j = 0; j < 4; j++)                               \
                if (j < nslots) cp16(sdst[j] + bo, ssrc[j] + co);     \
            asm volatile("cp.async.commit_group;" ::: "memory");      \
        } while (0)

    // 27 accumulators: pair over the 2 pixels
    ull acc[3][9];
    #pragma unroll
    for (int t = 0; t < 3; t++)
        #pragma unroll
        for (int d = 0; d < 9; d++)
            acc[t][d] = 0ull;

    // compute-side smem float offsets (buffer 0, channel 0)
    const int jbase = ri + 8 - 3 * g;            // 2..10
    const int winf  = ri * W2 + x0;              // window floats x0..x0+9
    int af[3];
    #pragma unroll
    for (int t = 0; t < 3; t++)
        af[t] = (3 + jbase - t) * W2 + 4 + x0;

    FILL(0, 0);
    FILL(1, 1);

    int bufc = 0;   // s % 3
    int buff = 2;   // (s+2) % 3

    #pragma unroll 1
    for (int s = 0; s < STAGES; s++) {
        if (s < STAGES - 1)
            asm volatile("cp.async.wait_group 1;" ::: "memory");
        else
            asm volatile("cp.async.wait_group 0;" ::: "memory");
        __syncthreads();

        // fill buffer (s+2)%3 first: last consumed at stage s-1 (ordered by
        // the barrier above), and the LDGSTS overlap this stage's compute
        if (s + 2 < STAGES) FILL(buff, s + 2);

        const int boff = bufc * BUFF;
        #pragma unroll
        for (int u = 0; u < CHPS; u++) {
            const float* base = sm + boff + u * CHF;
            // window: 5 non-overlapping ull pairs = floats x0-4 .. x0+5
            const ull* uw = (const ull*)(base + winf);
            const ull u0 = uw[0], u1 = uw[1], u2 = uw[2], u3 = uw[3], u4 = uw[4];
            const ull A0 = *(const ull*)(base + af[0]);
            const ull A1 = *(const ull*)(base + af[1]);
            const ull A2 = *(const ull*)(base + af[2]);

            ull wp[9];
            wp[0] = u0;  wp[2] = u1;  wp[4] = u2;  wp[6] = u3;  wp[8] = u4;
            wp[1] = pkmid(u0, u1);
            wp[3] = pkmid(u1, u2);
            wp[5] = pkmid(u2, u3);
            wp[7] = pkmid(u3, u4);

            #pragma unroll
            for (int d = 0; d < 9; d++) {
                fma2(acc[0][d], A0, wp[d]);
                fma2(acc[1][d], A1, wp[d]);
                fma2(acc[2][d], A2, wp[d]);
            }
        }

        bufc = (bufc == 2) ? 0 : bufc + 1;
        buff = (buff == 2) ? 0 : buff + 1;
    }
    #undef FILL

    // ---- epilogue: x-boundary zeros came free from smem pads ----
    #pragma unroll
    for (int t = 0; t < 3; t++) {
        const int y = r + 4 - (3 * g + t);
        if (y < 0 || y >= HH) continue;        // warp-uniform
        const int dy = 3 * g + t;
        #pragma unroll
        for (int d = 0; d < 9; d++) {
            const float2 v = unpk(acc[t][d]);
            float* po = out + (((((size_t)b * 9 + dy) * 9 + d) * HH + y) * WW) + x0;
            *(float2*)po = make_float2(v.x * rowok, v.y * rowok);
        }
    }
}

extern "C" void kernel_launch(void* const* d_in, const int* in_sizes, int n_in,
                              void* d_out, int out_size)
{
    const float* in1 = (const float*)d_in[0];
    const float* in2 = (const float*)d_in[1];
    float* out = (float*)d_out;

    // dynamic smem > 48 KB needs an explicit opt-in (host attr, capture-safe)
    cudaFuncSetAttribute(corr_kernel,
                         cudaFuncAttributeMaxDynamicSharedMemorySize, SMEMB);

    // blockIdx.x = r-tile (35 tiles cover r = -4..100), blockIdx.y = batch
    dim3 grid(35, 8, 1);
    corr_kernel<<<grid, NTHR, SMEMB>>>(in1, in2, out);
}